// round 8
// baseline (speedup 1.0000x reference)
#include <cuda_runtime.h>
#include <cuda_bf16.h>

// LengthRegulator: out[b,t,:] = x[b, searchsorted(cumsum(dur[b]), t, 'right'), :]
// (zeros for t >= total duration). Shapes fixed by the problem:
//   x: [16, 512, 512] f32, durations: [16, 512] i32, out: [16, 4096, 512] f32.
//
// R7 structure (best: streaming stores smooth the DRAM writeback across the
// replay period) + PDL: gather launches programmatically-dependent on scan,
// so scan execution + gather launch latency overlap with gather dispatch.

static constexpr int B  = 16;
static constexpr int S  = 512;
static constexpr int H  = 512;
static constexpr int T  = 4096;
static constexpr int H4 = H / 4;          // 128 float4 per row

// Scratch: per-frame source-token index (S means "invalid / zero frame").
__device__ int g_idx[B * T];

// One block per batch. Warp-shuffle inclusive scan, then scatter: token j
// writes its index over frames [cum[j-1], cum[j]); tail gets S. Signals
// dependent launch once this block's g_idx stores are done.
__global__ void scan_idx_kernel(const int* __restrict__ durations) {
    __shared__ int warp_sums[16];
    __shared__ int s_total;
    const int b    = blockIdx.x;
    const int tid  = threadIdx.x;         // blockDim.x == S == 512
    const int lane = tid & 31;
    const int wid  = tid >> 5;            // 16 warps

    const int d = durations[b * S + tid];

    int v = d;
    #pragma unroll
    for (int off = 1; off < 32; off <<= 1) {
        int n = __shfl_up_sync(0xffffffffu, v, off);
        if (lane >= off) v += n;
    }
    if (lane == 31) warp_sums[wid] = v;
    __syncthreads();

    if (wid == 0 && lane < 16) {
        int w = warp_sums[lane];
        #pragma unroll
        for (int off = 1; off < 16; off <<= 1) {
            int n = __shfl_up_sync(0xffffu, w, off);
            if (lane >= off) w += n;
        }
        warp_sums[lane] = w;
        if (lane == 15) s_total = w;
    }
    __syncthreads();

    const int cum   = v + (wid > 0 ? warp_sums[wid - 1] : 0);  // inclusive
    const int start = cum - d;                                  // exclusive
    const int total = s_total;
    int* __restrict__ gi = g_idx + b * T;

    for (int t = start; t < cum; ++t) gi[t] = tid;
    for (int t = total + tid; t < T; t += S) gi[t] = S;

    // Writes above become visible to the dependent grid past its wait.
    __syncthreads();
    asm volatile("griddepcontrol.launch_dependents;" ::: "memory");
}

// One WARP per PAIR of consecutive output rows; 4 float4s per lane per row.
// Warp-uniform idx1==idx0 fast path reuses registers (~87% of pairs).
// All output stores are streaming (evict-first).
__global__ void gather_kernel(const float4* __restrict__ x,
                              float4* __restrict__ out) {
    const int w    = blockIdx.x * (blockDim.x >> 5) + (threadIdx.x >> 5);
    const int row0 = w << 1;              // even; row1 = row0+1 (same batch)
    const int lane = threadIdx.x & 31;
    const int b    = row0 >> 12;          // / T

    // Block until the scan grid has published g_idx.
    asm volatile("griddepcontrol.wait;" ::: "memory");

    const int idx0 = g_idx[row0];
    const int idx1 = g_idx[row0 + 1];

    const float4 z = make_float4(0.f, 0.f, 0.f, 0.f);
    float4 a0 = z, a1 = z, a2 = z, a3 = z;
    float4 c0 = z, c1 = z, c2 = z, c3 = z;

    if (idx0 < S) {
        const float4* s = x + ((long long)((b << 9) + idx0) << 7);
        a0 = s[lane];      a1 = s[lane + 32];
        a2 = s[lane + 64]; a3 = s[lane + 96];
    }
    if (idx1 < S) {
        if (idx1 == idx0) {               // warp-uniform fast path
            c0 = a0; c1 = a1; c2 = a2; c3 = a3;
        } else {
            const float4* s = x + ((long long)((b << 9) + idx1) << 7);
            c0 = s[lane];      c1 = s[lane + 32];
            c2 = s[lane + 64]; c3 = s[lane + 96];
        }
    }

    float4* o0 = out + ((long long)row0 << 7);
    float4* o1 = o0 + H4;
    __stcs(&o0[lane],      a0);  __stcs(&o0[lane + 32], a1);
    __stcs(&o0[lane + 64], a2);  __stcs(&o0[lane + 96], a3);
    __stcs(&o1[lane],      c0);  __stcs(&o1[lane + 32], c1);
    __stcs(&o1[lane + 64], c2);  __stcs(&o1[lane + 96], c3);
}

extern "C" void kernel_launch(void* const* d_in, const int* in_sizes, int n_in,
                              void* d_out, int out_size) {
    const float* x   = (const float*)d_in[0];      // [B, S, H] f32
    const int*   dur = (const int*)d_in[1];        // [B, S]   i32
    float*       out = (float*)d_out;              // [B, T, H] f32
    (void)in_sizes; (void)n_in; (void)out_size;

    scan_idx_kernel<<<B, S>>>(dur);

    // Launch gather with programmatic stream serialization: it may begin
    // dispatching before scan fully retires; it self-synchronizes via
    // griddepcontrol.wait.
    const int threads = 256;                        // 8 warps = 16 rows/block
    const int blocks  = (B * T) / ((threads / 32) * 2);  // 4096

    cudaLaunchConfig_t cfg = {};
    cfg.gridDim  = dim3(blocks, 1, 1);
    cfg.blockDim = dim3(threads, 1, 1);
    cfg.dynamicSmemBytes = 0;
    cfg.stream = 0;
    cudaLaunchAttribute attr[1];
    attr[0].id = cudaLaunchAttributeProgrammaticStreamSerialization;
    attr[0].val.programmaticStreamSerializationAllowed = 1;
    cfg.attrs = attr;
    cfg.numAttrs = 1;

    cudaLaunchKernelEx(&cfg, gather_kernel, (const float4*)x, (float4*)out);
}